// round 10
// baseline (speedup 1.0000x reference)
#include <cuda_runtime.h>
#include <cstdint>

// ---------------------------------------------------------------------------
// GA (3,0,0) fused dense layer as one TF32 mma.sync GEMM.
//   out[k*B+b, d] = sum_j s(k,j) * ( X[i(k,j)*B+b, :] @ W[:, j*D+d] ) + bias[k*D+d]
// M=16384, N=2048, K=16384.
// R10: R8 config (2x 128-thread CTAs/SM, 64x64 warp tiles) + W transposed in
//      preprocessing -> B smem is [n][k] like A -> ldmatrix for BOTH operands.
// 6-stage cp.async ring, one barrier per 2 k-tiles, signs via A-frag XOR.
// ---------------------------------------------------------------------------

#define NTHREADS 128
#define BK 16
#define NKT 1024               // 16384 / BK
#define NPAIRS 512
#define ASZ 2048               // A words per stage: 128 rows x 16
#define BSZ 2048               // B words per stage: 128 n-rows x 16
#define STAGE_W (ASZ + BSZ)    // 4096 words = 16384 B
#define STAGES 6
#define SMEM_BYTES (STAGES * STAGE_W * 4)   // 98304 B per CTA -> 2 CTAs/SM

// 128 MB scratch each: tf32-rounded X, tf32-rounded TRANSPOSED W
__device__ float Xc[16384 * 2048];
__device__ float Wt[16384 * 2048];   // Wt[n][k] = W[k][n]

// ---------------- Cayley table (validated rounds 1-9) ----------------
__device__ __constant__ int c_kij[64] = {
    0,1,2,3,4,5,6,7,  1,0,4,5,2,3,7,6,  2,4,0,6,1,7,3,5,  3,5,6,0,7,1,2,4,
    4,2,1,7,0,6,5,3,  5,3,7,1,6,0,4,2,  6,7,3,2,5,4,0,1,  7,6,5,4,3,2,1,0};
__device__ __constant__ float c_sij[64] = {
    1.f, 1.f, 1.f, 1.f, 1.f, 1.f, 1.f, 1.f,
    1.f, 1.f, 1.f, 1.f, 1.f, 1.f, 1.f, 1.f,
    1.f,-1.f, 1.f, 1.f,-1.f,-1.f, 1.f,-1.f,
    1.f,-1.f,-1.f, 1.f, 1.f,-1.f,-1.f, 1.f,
    1.f,-1.f, 1.f, 1.f,-1.f,-1.f, 1.f,-1.f,
    1.f,-1.f,-1.f, 1.f, 1.f,-1.f,-1.f, 1.f,
    1.f, 1.f,-1.f, 1.f,-1.f, 1.f,-1.f,-1.f,
    1.f, 1.f,-1.f, 1.f,-1.f, 1.f,-1.f,-1.f};

__device__ __forceinline__ void gather_info(int kblk, int j, int& ib, float& sg) {
    int ibv = 0; float sv = 1.f;
#pragma unroll
    for (int ii = 0; ii < 8; ++ii) {
        bool m = (c_kij[ii * 8 + j] == kblk);
        ibv = m ? ii : ibv;
        sv  = m ? c_sij[ii * 8 + j] : sv;
    }
    ib = ibv; sg = sv;
}

__device__ __forceinline__ uint32_t f2tf32(float f) {
    uint32_t r;
    asm("cvt.rna.tf32.f32 %0, %1;" : "=r"(r) : "f"(f));
    return r;
}

__device__ __forceinline__ void mma_tf32(float* d, const uint32_t* a,
                                         uint32_t b0, uint32_t b1) {
    asm volatile(
        "mma.sync.aligned.m16n8k8.row.col.f32.tf32.tf32.f32 "
        "{%0,%1,%2,%3}, {%4,%5,%6,%7}, {%8,%9}, {%0,%1,%2,%3};"
        : "+f"(d[0]), "+f"(d[1]), "+f"(d[2]), "+f"(d[3])
        : "r"(a[0]), "r"(a[1]), "r"(a[2]), "r"(a[3]), "r"(b0), "r"(b1));
}

__device__ __forceinline__ void ldsm4(uint32_t* r, uint32_t addr) {
    asm volatile("ldmatrix.sync.aligned.m8n8.x4.shared.b16 {%0,%1,%2,%3}, [%4];"
        : "=r"(r[0]), "=r"(r[1]), "=r"(r[2]), "=r"(r[3]) : "r"(addr));
}

__device__ __forceinline__ uint32_t smem_u32(const void* p) {
    uint32_t a;
    asm("{ .reg .u64 t; cvta.to.shared.u64 t, %1; cvt.u32.u64 %0, t; }" : "=r"(a) : "l"(p));
    return a;
}

__device__ __forceinline__ void cp16(uint32_t dst, const float* src) {
    asm volatile("cp.async.cg.shared.global [%0], [%1], 16;" :: "r"(dst), "l"(src) : "memory");
}
#define CP_COMMIT()  asm volatile("cp.async.commit_group;" ::: "memory")
#define CP_WAIT(n)   asm volatile("cp.async.wait_group %0;" :: "n"(n) : "memory")

// ---------------------------------------------------------------------------
// Preprocess 1: round X to tf32 (RN).
__global__ __launch_bounds__(256)
void preconv_x(const float* __restrict__ X)
{
    const size_t i = ((size_t)blockIdx.x * 256 + threadIdx.x) * 4;
    float4 x = *reinterpret_cast<const float4*>(X + i);
    x.x = __uint_as_float(f2tf32(x.x)); x.y = __uint_as_float(f2tf32(x.y));
    x.z = __uint_as_float(f2tf32(x.z)); x.w = __uint_as_float(f2tf32(x.w));
    *reinterpret_cast<float4*>(Xc + i) = x;
}

// Preprocess 2: transpose W [2048,16384] -> Wt [16384,2048], rounding to tf32.
__global__ __launch_bounds__(256)
void preconv_wt(const float* __restrict__ W)
{
    __shared__ float tile[32][33];
    const int n0 = blockIdx.x * 32;      // 512 blocks
    const int k0 = blockIdx.y * 32;      // 64 blocks
    const int x = threadIdx.x;           // 0..31
    const int y = threadIdx.y;           // 0..7
#pragma unroll
    for (int i = 0; i < 4; ++i)
        tile[y + 8 * i][x] = W[(size_t)(k0 + y + 8 * i) * 16384 + n0 + x];
    __syncthreads();
#pragma unroll
    for (int i = 0; i < 4; ++i)
        Wt[(size_t)(n0 + y + 8 * i) * 2048 + k0 + x] =
            __uint_as_float(f2tf32(tile[x][y + 8 * i]));
}

// ---------------------------------------------------------------------------
__global__ __launch_bounds__(NTHREADS, 2)
void ga_tf32_mma8(const float* __restrict__ bias,  // [16384]
                  float* __restrict__ out)         // [16384, 2048]
{
    extern __shared__ uint32_t sm[];
    const uint32_t sb = smem_u32(sm);

    const int tid  = threadIdx.x;
    const int wid  = tid >> 5;
    const int lane = tid & 31;
    const int q    = lane & 3;
    const int g    = lane >> 2;
    const int wm   = wid >> 1;      // 0..1 (M warps, 64 rows each)
    const int wn   = wid & 1;       // 0..1 (N warps, 64 cols each)

    const int bn   = blockIdx.x;    // 0..15  N tiles (128 wide)
    const int bm   = blockIdx.y;    // 0..127 M tiles (128 tall)
    const int kblk = bm >> 4;       // output blade
    const int rloc = (bm & 15) * 128;

    int      ibA[8];
    uint32_t signbits = 0;
#pragma unroll
    for (int j = 0; j < 8; ++j) {
        int ib; float sg;
        gather_info(kblk, j, ib, sg);
        ibA[j] = ib;
        if (sg < 0.f) signbits |= (1u << j);
    }

    float acc[4][8][4];
#pragma unroll
    for (int f = 0; f < 4; ++f)
#pragma unroll
        for (int n = 0; n < 8; ++n)
#pragma unroll
            for (int e = 0; e < 4; ++e) acc[f][n][e] = 0.f;

    // ---- ldmatrix per-lane address precompute (A and B fragments) ----
    // x4: sub0 rows r0..r0+7 chunk lo | sub1 rows +8 chunk lo | sub2/3 chunk hi
    const int sub    = lane >> 3;
    const int hi     = sub >> 1;
    const int rowoff = (lane & 7) + (sub & 1) * 8;
    uint32_t rbyteA[4]; int sxA[4];
#pragma unroll
    for (int f = 0; f < 4; ++f) {
        const int r = wm * 64 + f * 16 + rowoff;
        rbyteA[f] = (uint32_t)(r * 64);
        sxA[f]    = (r >> 1) & 3;
    }
    uint32_t rbyteB[4]; int sxB[4];
#pragma unroll
    for (int n2 = 0; n2 < 4; ++n2) {
        const int r = wn * 64 + n2 * 16 + rowoff;
        rbyteB[n2] = (uint32_t)(r * 64);
        sxB[n2]    = (r >> 1) & 3;
    }

    // cp.async thread mappings (identical pattern for A and B: 128 rows x 16 w)
    const int c_row = tid >> 2;      // 0..31 (+32*i)
    const int c_ch  = tid & 3;       // k-chunk

    auto issue_tile = [&](int kt) {
        const int s  = kt % STAGES;
        const int j  = kt >> 7;
        const int c0 = (kt & 127) * BK;
        const uint32_t As = sb + (uint32_t)(s * STAGE_W * 4);
        const uint32_t Bs = As + ASZ * 4;
        const float* Ap = Xc + ((size_t)(ibA[j] * 2048 + rloc)) * 2048 + c0 + c_ch * 4;
#pragma unroll
        for (int i = 0; i < 4; ++i) {
            const int m  = c_row + 32 * i;
            const int ch = c_ch ^ ((m >> 1) & 3);
            cp16(As + (uint32_t)((m * 16 + ch * 4) * 4), Ap + (size_t)m * 2048);
        }
        // B from transposed weights: rows are n (global n = j*2048 + bn*128 + nr)
        const float* Bp = Wt + ((size_t)(j * 2048 + bn * 128)) * 2048 + c0 + c_ch * 4;
#pragma unroll
        for (int i = 0; i < 4; ++i) {
            const int nr = c_row + 32 * i;
            const int ch = c_ch ^ ((nr >> 1) & 3);
            cp16(Bs + (uint32_t)((nr * 16 + ch * 4) * 4), Bp + (size_t)nr * 2048);
        }
    };

    auto compute_tile = [&](int kt) {
        const int s = kt % STAGES;
        const uint32_t AsAddr = sb + (uint32_t)(s * STAGE_W * 4);
        const uint32_t BsAddr = AsAddr + (uint32_t)(ASZ * 4);
        const uint32_t smask = ((signbits >> (kt >> 7)) & 1u) << 31;
#pragma unroll
        for (int ks = 0; ks < 2; ++ks) {
            uint32_t afr[4][4], bt[4][4];
#pragma unroll
            for (int f = 0; f < 4; ++f) {
                const int ch = (2 * ks + hi) ^ sxA[f];
                ldsm4(afr[f], AsAddr + rbyteA[f] + (uint32_t)(ch * 16));
            }
#pragma unroll
            for (int n2 = 0; n2 < 4; ++n2) {
                const int ch = (2 * ks + hi) ^ sxB[n2];
                ldsm4(bt[n2], BsAddr + rbyteB[n2] + (uint32_t)(ch * 16));
            }
#pragma unroll
            for (int f = 0; f < 4; ++f) {
                afr[f][0] ^= smask; afr[f][1] ^= smask;
                afr[f][2] ^= smask; afr[f][3] ^= smask;
            }
            // bt[n2]: r0 = b0(nf=2*n2), r1 = b0(nf=2*n2+1), r2 = b1(2*n2), r3 = b1(2*n2+1)
#pragma unroll
            for (int f = 0; f < 4; ++f)
#pragma unroll
                for (int n2 = 0; n2 < 4; ++n2) {
                    mma_tf32(acc[f][2 * n2    ], afr[f], bt[n2][0], bt[n2][2]);
                    mma_tf32(acc[f][2 * n2 + 1], afr[f], bt[n2][1], bt[n2][3]);
                }
        }
    };

    // prologue: pairs 0 and 1 (tiles 0..3), one commit group per pair
    issue_tile(0); issue_tile(1); CP_COMMIT();
    issue_tile(2); issue_tile(3); CP_COMMIT();

    for (int p = 0; p < NPAIRS; ++p) {
        if (p < NPAIRS - 1) { CP_WAIT(1); } else { CP_WAIT(0); }
        __syncthreads();     // single barrier per pair; protects stage reuse

        if (p + 2 < NPAIRS) {
            issue_tile(2 * p + 4);
            issue_tile(2 * p + 5);
            CP_COMMIT();
        }

        compute_tile(2 * p);
        compute_tile(2 * p + 1);
        // no trailing barrier: next iteration's writes target pair p-1's
        // stages, which every warp finished before this iteration's barrier.
    }

    // ---- epilogue: add blade bias, store ----
    const int ccol = bn * 128 + wn * 64;
    const float* bp = bias + (size_t)kblk * 2048 + ccol;

#pragma unroll
    for (int nf = 0; nf < 8; ++nf) {
        const int cn = nf * 8 + 2 * q;
        const float b0 = bp[cn], b1 = bp[cn + 1];
#pragma unroll
        for (int f = 0; f < 4; ++f) {
            const int r0 = bm * 128 + wm * 64 + f * 16 + g;
            float2 lo  = make_float2(acc[f][nf][0] + b0, acc[f][nf][1] + b1);
            float2 hi2 = make_float2(acc[f][nf][2] + b0, acc[f][nf][3] + b1);
            *reinterpret_cast<float2*>(out + (size_t)r0 * 2048 + ccol + cn)       = lo;
            *reinterpret_cast<float2*>(out + (size_t)(r0 + 8) * 2048 + ccol + cn) = hi2;
        }
    }
}

extern "C" void kernel_launch(void* const* d_in, const int* in_sizes, int n_in,
                              void* d_out, int out_size)
{
    const float* X    = (const float*)d_in[0];
    const float* W    = (const float*)d_in[1];
    const float* bias = (const float*)d_in[2];
    float* out        = (float*)d_out;

    preconv_x<<<32768, 256>>>(X);
    preconv_wt<<<dim3(512, 64), dim3(32, 8)>>>(W);

    cudaFuncSetAttribute(ga_tf32_mma8, cudaFuncAttributeMaxDynamicSharedMemorySize, SMEM_BYTES);
    dim3 grid(16, 128);
    ga_tf32_mma8<<<grid, NTHREADS, SMEM_BYTES>>>(bias, out);
}

// round 11
// speedup vs baseline: 1.1568x; 1.1568x over previous
#include <cuda_runtime.h>
#include <cstdint>

// ---------------------------------------------------------------------------
// GA (3,0,0) fused dense layer as one TF32 mma.sync GEMM.
//   out[k*B+b, d] = sum_j s(k,j) * ( X[i(k,j)*B+b, :] @ W[:, j*D+d] ) + bias[k*D+d]
// M=16384, N=2048, K=16384.
// R11 = R8 (best: 2x 128-thread CTAs/SM, 64x64 warp tiles, ldmatrix A,
//       LDS B k-major, 6-stage cp.async ring, 1 barrier / 2 k-tiles)
//       + pre-negated X copy: sign selects the A base pointer, the mainloop
//       has ZERO sign instructions (removes ldsm->XOR->mma dependency).
// ---------------------------------------------------------------------------

#define NTHREADS 128
#define BK 16
#define NKT 1024               // 16384 / BK
#define NPAIRS 512
#define ASZ 2048               // A words per stage: 128*16
#define BSTRIDE 136            // B words per k-row (128 + 8 pad; 136 mod 32 == 8)
#define BSZ (16 * BSTRIDE)     // 2176 words
#define STAGE_W (ASZ + BSZ)    // 4224 words = 16896 B
#define STAGES 6
#define SMEM_BYTES (STAGES * STAGE_W * 4)   // 101376 B per CTA -> 2 CTAs/SM

// scratch: tf32-rounded X, its negation, tf32-rounded W
__device__ float Xc[16384 * 2048];
__device__ float Xn[16384 * 2048];
__device__ float Wc[2048 * 16384];

// ---------------- Cayley table (validated rounds 1-10) ----------------
__device__ __constant__ int c_kij[64] = {
    0,1,2,3,4,5,6,7,  1,0,4,5,2,3,7,6,  2,4,0,6,1,7,3,5,  3,5,6,0,7,1,2,4,
    4,2,1,7,0,6,5,3,  5,3,7,1,6,0,4,2,  6,7,3,2,5,4,0,1,  7,6,5,4,3,2,1,0};
__device__ __constant__ float c_sij[64] = {
    1.f, 1.f, 1.f, 1.f, 1.f, 1.f, 1.f, 1.f,
    1.f, 1.f, 1.f, 1.f, 1.f, 1.f, 1.f, 1.f,
    1.f,-1.f, 1.f, 1.f,-1.f,-1.f, 1.f,-1.f,
    1.f,-1.f,-1.f, 1.f, 1.f,-1.f,-1.f, 1.f,
    1.f,-1.f, 1.f, 1.f,-1.f,-1.f, 1.f,-1.f,
    1.f,-1.f,-1.f, 1.f, 1.f,-1.f,-1.f, 1.f,
    1.f, 1.f,-1.f, 1.f,-1.f, 1.f,-1.f,-1.f,
    1.f, 1.f,-1.f, 1.f,-1.f, 1.f,-1.f,-1.f};

__device__ __forceinline__ void gather_info(int kblk, int j, int& ib, float& sg) {
    int ibv = 0; float sv = 1.f;
#pragma unroll
    for (int ii = 0; ii < 8; ++ii) {
        bool m = (c_kij[ii * 8 + j] == kblk);
        ibv = m ? ii : ibv;
        sv  = m ? c_sij[ii * 8 + j] : sv;
    }
    ib = ibv; sg = sv;
}

__device__ __forceinline__ uint32_t f2tf32(float f) {
    uint32_t r;
    asm("cvt.rna.tf32.f32 %0, %1;" : "=r"(r) : "f"(f));
    return r;
}

__device__ __forceinline__ void mma_tf32(float* d, const uint32_t* a, const uint32_t* b) {
    asm volatile(
        "mma.sync.aligned.m16n8k8.row.col.f32.tf32.tf32.f32 "
        "{%0,%1,%2,%3}, {%4,%5,%6,%7}, {%8,%9}, {%0,%1,%2,%3};"
        : "+f"(d[0]), "+f"(d[1]), "+f"(d[2]), "+f"(d[3])
        : "r"(a[0]), "r"(a[1]), "r"(a[2]), "r"(a[3]), "r"(b[0]), "r"(b[1]));
}

__device__ __forceinline__ void ldsm4(uint32_t* r, uint32_t addr) {
    asm volatile("ldmatrix.sync.aligned.m8n8.x4.shared.b16 {%0,%1,%2,%3}, [%4];"
        : "=r"(r[0]), "=r"(r[1]), "=r"(r[2]), "=r"(r[3]) : "r"(addr));
}

__device__ __forceinline__ uint32_t smem_u32(const void* p) {
    uint32_t a;
    asm("{ .reg .u64 t; cvta.to.shared.u64 t, %1; cvt.u32.u64 %0, t; }" : "=r"(a) : "l"(p));
    return a;
}

__device__ __forceinline__ void cp16(uint32_t dst, const float* src) {
    asm volatile("cp.async.cg.shared.global [%0], [%1], 16;" :: "r"(dst), "l"(src) : "memory");
}
#define CP_COMMIT()  asm volatile("cp.async.commit_group;" ::: "memory")
#define CP_WAIT(n)   asm volatile("cp.async.wait_group %0;" :: "n"(n) : "memory")

// ---------------------------------------------------------------------------
// Preprocess: round X/W to tf32 (RN); also write the negated X copy.
__global__ __launch_bounds__(256)
void preconv_tf32(const float* __restrict__ X, const float* __restrict__ W)
{
    const size_t i = ((size_t)blockIdx.x * 256 + threadIdx.x) * 4;
    float4 x = *reinterpret_cast<const float4*>(X + i);
    x.x = __uint_as_float(f2tf32(x.x)); x.y = __uint_as_float(f2tf32(x.y));
    x.z = __uint_as_float(f2tf32(x.z)); x.w = __uint_as_float(f2tf32(x.w));
    *reinterpret_cast<float4*>(Xc + i) = x;
    float4 xn = make_float4(-x.x, -x.y, -x.z, -x.w);
    *reinterpret_cast<float4*>(Xn + i) = xn;
    float4 w = *reinterpret_cast<const float4*>(W + i);
    w.x = __uint_as_float(f2tf32(w.x)); w.y = __uint_as_float(f2tf32(w.y));
    w.z = __uint_as_float(f2tf32(w.z)); w.w = __uint_as_float(f2tf32(w.w));
    *reinterpret_cast<float4*>(Wc + i) = w;
}

// ---------------------------------------------------------------------------
__global__ __launch_bounds__(NTHREADS, 2)
void ga_tf32_mma9(const float* __restrict__ bias,  // [16384]
                  float* __restrict__ out)         // [16384, 2048]
{
    extern __shared__ uint32_t sm[];
    const uint32_t sb = smem_u32(sm);

    const int tid  = threadIdx.x;
    const int wid  = tid >> 5;
    const int lane = tid & 31;
    const int q    = lane & 3;
    const int g    = lane >> 2;
    const int wm   = wid >> 1;      // 0..1 (M warps, 64 rows each)
    const int wn   = wid & 1;       // 0..1 (N warps, 64 cols each)

    const int bn   = blockIdx.x;    // 0..15  N tiles (128 wide)
    const int bm   = blockIdx.y;    // 0..127 M tiles (128 tall)
    const int kblk = bm >> 4;       // output blade
    const int rloc = (bm & 15) * 128;

    // per-j A base pointer: sign baked in by selecting Xc vs Xn
    const float* ApBase[8];
#pragma unroll
    for (int j = 0; j < 8; ++j) {
        int ib; float sg;
        gather_info(kblk, j, ib, sg);
        const float* base = (sg > 0.f) ? Xc : Xn;
        ApBase[j] = base + ((size_t)(ib * 2048 + rloc)) * 2048;
    }

    float acc[4][8][4];
#pragma unroll
    for (int f = 0; f < 4; ++f)
#pragma unroll
        for (int n = 0; n < 8; ++n)
#pragma unroll
            for (int e = 0; e < 4; ++e) acc[f][n][e] = 0.f;

    // ---- ldmatrix per-lane address precompute (A fragments) ----
    const int sub    = lane >> 3;
    const int hi     = sub >> 1;
    const int rowoff = (lane & 7) + (sub & 1) * 8;
    uint32_t rbyte[4];
    int      sx[4];
#pragma unroll
    for (int f = 0; f < 4; ++f) {
        const int r = wm * 64 + f * 16 + rowoff;
        rbyte[f] = (uint32_t)(r * 64);
        sx[f]    = (r >> 1) & 3;
    }

    // cp.async thread mappings
    const int a_m = tid >> 2;        // 0..31 (+32*i)
    const int a_c = tid & 3;
    const int b_k = tid >> 5;        // 0..3  (+4*i)
    const int b_n = (tid & 31) * 4;

    auto issue_tile = [&](int kt) {
        const int s  = kt % STAGES;
        const int j  = kt >> 7;
        const int c0 = (kt & 127) * BK;
        const uint32_t As = sb + (uint32_t)(s * STAGE_W * 4);
        const uint32_t Bs = As + ASZ * 4;
        const float* Ap = ApBase[j] + c0 + a_c * 4;
#pragma unroll
        for (int i = 0; i < 4; ++i) {
            const int m  = a_m + 32 * i;
            const int ch = a_c ^ ((m >> 1) & 3);
            cp16(As + (uint32_t)((m * 16 + ch * 4) * 4), Ap + (size_t)m * 2048);
        }
        const float* Bp = Wc + (size_t)c0 * 16384 + (size_t)j * 2048 + bn * 128 + b_n;
#pragma unroll
        for (int i = 0; i < 4; ++i)
            cp16(Bs + (uint32_t)(((b_k + 4 * i) * BSTRIDE + b_n) * 4),
                 Bp + (size_t)(b_k + 4 * i) * 16384);
    };

    auto compute_tile = [&](int kt) {
        const int s = kt % STAGES;
        const uint32_t AsAddr = sb + (uint32_t)(s * STAGE_W * 4);
        const uint32_t* Bs = sm + s * STAGE_W + ASZ;
#pragma unroll
        for (int ks = 0; ks < 2; ++ks) {
            uint32_t afr[4][4], bfr[8][2];
#pragma unroll
            for (int f = 0; f < 4; ++f) {
                const int ch = (2 * ks + hi) ^ sx[f];
                ldsm4(afr[f], AsAddr + rbyte[f] + (uint32_t)(ch * 16));
            }
#pragma unroll
            for (int nf = 0; nf < 8; ++nf) {
                const int n0 = wn * 64 + nf * 8 + g;
                bfr[nf][0] = Bs[(ks * 8 + q    ) * BSTRIDE + n0];
                bfr[nf][1] = Bs[(ks * 8 + q + 4) * BSTRIDE + n0];
            }
#pragma unroll
            for (int f = 0; f < 4; ++f)
#pragma unroll
                for (int nf = 0; nf < 8; ++nf)
                    mma_tf32(acc[f][nf], afr[f], bfr[nf]);
        }
    };

    // prologue: pairs 0 and 1 (tiles 0..3), one commit group per pair
    issue_tile(0); issue_tile(1); CP_COMMIT();
    issue_tile(2); issue_tile(3); CP_COMMIT();

    for (int p = 0; p < NPAIRS; ++p) {
        if (p < NPAIRS - 1) { CP_WAIT(1); } else { CP_WAIT(0); }
        __syncthreads();     // single barrier per pair; protects stage reuse

        if (p + 2 < NPAIRS) {
            issue_tile(2 * p + 4);
            issue_tile(2 * p + 5);
            CP_COMMIT();
        }

        compute_tile(2 * p);
        compute_tile(2 * p + 1);
        // no trailing barrier: next iteration's writes target pair p-1's
        // stages, which every warp finished before this iteration's barrier.
    }

    // ---- epilogue: add blade bias, store ----
    const int ccol = bn * 128 + wn * 64;
    const float* bp = bias + (size_t)kblk * 2048 + ccol;

#pragma unroll
    for (int nf = 0; nf < 8; ++nf) {
        const int cn = nf * 8 + 2 * q;
        const float b0 = bp[cn], b1 = bp[cn + 1];
#pragma unroll
        for (int f = 0; f < 4; ++f) {
            const int r0 = bm * 128 + wm * 64 + f * 16 + g;
            float2 lo  = make_float2(acc[f][nf][0] + b0, acc[f][nf][1] + b1);
            float2 hi2 = make_float2(acc[f][nf][2] + b0, acc[f][nf][3] + b1);
            *reinterpret_cast<float2*>(out + (size_t)r0 * 2048 + ccol + cn)       = lo;
            *reinterpret_cast<float2*>(out + (size_t)(r0 + 8) * 2048 + ccol + cn) = hi2;
        }
    }
}

extern "C" void kernel_launch(void* const* d_in, const int* in_sizes, int n_in,
                              void* d_out, int out_size)
{
    const float* X    = (const float*)d_in[0];
    const float* W    = (const float*)d_in[1];
    const float* bias = (const float*)d_in[2];
    float* out        = (float*)d_out;

    preconv_tf32<<<32768, 256>>>(X, W);

    cudaFuncSetAttribute(ga_tf32_mma9, cudaFuncAttributeMaxDynamicSharedMemorySize, SMEM_BYTES);
    dim3 grid(16, 128);
    ga_tf32_mma9<<<grid, NTHREADS, SMEM_BYTES>>>(bias, out);
}

// round 12
// speedup vs baseline: 2.6844x; 2.3205x over previous
#include <cuda_runtime.h>
#include <cuda_fp16.h>
#include <cstdint>

// ---------------------------------------------------------------------------
// GA (3,0,0) fused dense layer as one FP16 mma.sync GEMM (fp32 accumulate).
//   out[k*B+b, d] = sum_j s(k,j) * ( X[i(k,j)*B+b, :] @ W[:, j*D+d] ) + bias[k*D+d]
// M=16384, N=2048, K=16384.
// R12: fp16 m16n8k16 (same 10-bit mantissa as tf32 -> same rel_err, 2x rate).
// R11 skeleton: 2x 128-thread CTAs/SM, 64x64 warp tiles, 6-stage cp.async
// ring, 1 barrier / 2 k-tiles, sign via pre-negated X pointer table.
// A via ldmatrix.x4, B via ldmatrix.x4.trans. Zero scalar LDS in mainloop.
// ---------------------------------------------------------------------------

#define NTHREADS 128
#define BK 16
#define NKT 1024               // 16384 / BK
#define NPAIRS 512
#define ASZB 4096              // A stage bytes: 128 rows x 16 k x 2B
#define BSZB 4096              // B stage bytes: 16 k x 128 n x 2B
#define STAGE_B (ASZB + BSZB)  // 8192 B
#define STAGES 6
#define SMEM_BYTES (STAGES * STAGE_B)   // 49152 B per CTA

// 64 MB scratch each: fp16 X, -X, W
__device__ __half Xh[16384 * 2048];
__device__ __half Xn[16384 * 2048];
__device__ __half Wh[2048 * 16384];

// ---------------- Cayley table (validated rounds 1-11) ----------------
__device__ __constant__ int c_kij[64] = {
    0,1,2,3,4,5,6,7,  1,0,4,5,2,3,7,6,  2,4,0,6,1,7,3,5,  3,5,6,0,7,1,2,4,
    4,2,1,7,0,6,5,3,  5,3,7,1,6,0,4,2,  6,7,3,2,5,4,0,1,  7,6,5,4,3,2,1,0};
__device__ __constant__ float c_sij[64] = {
    1.f, 1.f, 1.f, 1.f, 1.f, 1.f, 1.f, 1.f,
    1.f, 1.f, 1.f, 1.f, 1.f, 1.f, 1.f, 1.f,
    1.f,-1.f, 1.f, 1.f,-1.f,-1.f, 1.f,-1.f,
    1.f,-1.f,-1.f, 1.f, 1.f,-1.f,-1.f, 1.f,
    1.f,-1.f, 1.f, 1.f,-1.f,-1.f, 1.f,-1.f,
    1.f,-1.f,-1.f, 1.f, 1.f,-1.f,-1.f, 1.f,
    1.f, 1.f,-1.f, 1.f,-1.f, 1.f,-1.f,-1.f,
    1.f, 1.f,-1.f, 1.f,-1.f, 1.f,-1.f,-1.f};

__device__ __forceinline__ void gather_info(int kblk, int j, int& ib, float& sg) {
    int ibv = 0; float sv = 1.f;
#pragma unroll
    for (int ii = 0; ii < 8; ++ii) {
        bool m = (c_kij[ii * 8 + j] == kblk);
        ibv = m ? ii : ibv;
        sv  = m ? c_sij[ii * 8 + j] : sv;
    }
    ib = ibv; sg = sv;
}

__device__ __forceinline__ void mma_f16(float* d, const uint32_t* a,
                                        uint32_t b0, uint32_t b1) {
    asm volatile(
        "mma.sync.aligned.m16n8k16.row.col.f32.f16.f16.f32 "
        "{%0,%1,%2,%3}, {%4,%5,%6,%7}, {%8,%9}, {%0,%1,%2,%3};"
        : "+f"(d[0]), "+f"(d[1]), "+f"(d[2]), "+f"(d[3])
        : "r"(a[0]), "r"(a[1]), "r"(a[2]), "r"(a[3]), "r"(b0), "r"(b1));
}

__device__ __forceinline__ void ldsm4(uint32_t* r, uint32_t addr) {
    asm volatile("ldmatrix.sync.aligned.m8n8.x4.shared.b16 {%0,%1,%2,%3}, [%4];"
        : "=r"(r[0]), "=r"(r[1]), "=r"(r[2]), "=r"(r[3]) : "r"(addr));
}
__device__ __forceinline__ void ldsm4t(uint32_t* r, uint32_t addr) {
    asm volatile("ldmatrix.sync.aligned.m8n8.x4.trans.shared.b16 {%0,%1,%2,%3}, [%4];"
        : "=r"(r[0]), "=r"(r[1]), "=r"(r[2]), "=r"(r[3]) : "r"(addr));
}

__device__ __forceinline__ uint32_t smem_u32(const void* p) {
    uint32_t a;
    asm("{ .reg .u64 t; cvta.to.shared.u64 t, %1; cvt.u32.u64 %0, t; }" : "=r"(a) : "l"(p));
    return a;
}

__device__ __forceinline__ void cp16(uint32_t dst, const void* src) {
    asm volatile("cp.async.cg.shared.global [%0], [%1], 16;" :: "r"(dst), "l"(src) : "memory");
}
#define CP_COMMIT()  asm volatile("cp.async.commit_group;" ::: "memory")
#define CP_WAIT(n)   asm volatile("cp.async.wait_group %0;" :: "n"(n) : "memory")

// ---------------------------------------------------------------------------
// Preprocess: X/W -> fp16 (RN), plus negated X. 8 elements per thread.
__global__ __launch_bounds__(256)
void preconv_h(const float* __restrict__ X, const float* __restrict__ W)
{
    const size_t i = ((size_t)blockIdx.x * 256 + threadIdx.x) * 8;
    {
        float4 x0 = *reinterpret_cast<const float4*>(X + i);
        float4 x1 = *reinterpret_cast<const float4*>(X + i + 4);
        __half2 h[4];
        h[0] = __floats2half2_rn(x0.x, x0.y);
        h[1] = __floats2half2_rn(x0.z, x0.w);
        h[2] = __floats2half2_rn(x1.x, x1.y);
        h[3] = __floats2half2_rn(x1.z, x1.w);
        *reinterpret_cast<uint4*>(Xh + i) = *reinterpret_cast<uint4*>(h);
        __half2 hn[4];
#pragma unroll
        for (int t = 0; t < 4; ++t) hn[t] = __hneg2(h[t]);
        *reinterpret_cast<uint4*>(Xn + i) = *reinterpret_cast<uint4*>(hn);
    }
    {
        float4 w0 = *reinterpret_cast<const float4*>(W + i);
        float4 w1 = *reinterpret_cast<const float4*>(W + i + 4);
        __half2 h[4];
        h[0] = __floats2half2_rn(w0.x, w0.y);
        h[1] = __floats2half2_rn(w0.z, w0.w);
        h[2] = __floats2half2_rn(w1.x, w1.y);
        h[3] = __floats2half2_rn(w1.z, w1.w);
        *reinterpret_cast<uint4*>(Wh + i) = *reinterpret_cast<uint4*>(h);
    }
}

// ---------------------------------------------------------------------------
__global__ __launch_bounds__(NTHREADS, 2)
void ga_f16_mma(const float* __restrict__ bias,  // [16384]
                float* __restrict__ out)         // [16384, 2048]
{
    extern __shared__ uint32_t sm[];
    const uint32_t sb = smem_u32(sm);

    const int tid  = threadIdx.x;
    const int wid  = tid >> 5;
    const int lane = tid & 31;
    const int q    = lane & 3;
    const int g    = lane >> 2;
    const int wm   = wid >> 1;      // 0..1 (M warps, 64 rows each)
    const int wn   = wid & 1;       // 0..1 (N warps, 64 cols each)

    const int bn   = blockIdx.x;    // 0..15  N tiles (128 wide)
    const int bm   = blockIdx.y;    // 0..127 M tiles (128 tall)
    const int kblk = bm >> 4;       // output blade
    const int rloc = (bm & 15) * 128;

    // per-j A base pointer: sign baked in by selecting Xh vs Xn
    const __half* ApBase[8];
#pragma unroll
    for (int j = 0; j < 8; ++j) {
        int ib; float sg;
        gather_info(kblk, j, ib, sg);
        const __half* base = (sg > 0.f) ? Xh : Xn;
        ApBase[j] = base + ((size_t)(ib * 2048 + rloc)) * 2048;
    }

    float acc[4][8][4];
#pragma unroll
    for (int f = 0; f < 4; ++f)
#pragma unroll
        for (int n = 0; n < 8; ++n)
#pragma unroll
            for (int e = 0; e < 4; ++e) acc[f][n][e] = 0.f;

    // ---- ldmatrix per-lane precompute ----
    // shared lane decomposition: rowoff covers matrices {lo rows, hi rows},
    // top half of the warp reads the second k/n 16B chunk.
    const int rowoff = (lane & 7) + ((lane >> 3) & 1) * 8;
    const int csel   = lane >> 4;                 // 0/1: second chunk

    // A: row r -> byte r*32, stored chunk = logical ^ ((r>>2)&1)
    uint32_t aAddrOff[4];
#pragma unroll
    for (int f = 0; f < 4; ++f) {
        const int r = wm * 64 + f * 16 + rowoff;
        const int ch = csel ^ ((r >> 2) & 1);
        aAddrOff[f] = (uint32_t)(r * 32 + ch * 16);
    }
    // B: k-row kB -> byte kB*256, chunk c stored at c ^ (kB & 7)
    const int kB = rowoff;
    uint32_t bAddrOff[4];
#pragma unroll
    for (int t = 0; t < 4; ++t) {
        const int c = wn * 8 + t * 2 + csel;
        bAddrOff[t] = (uint32_t)(kB * 256 + ((c ^ (kB & 7)) * 16));
    }

    // cp.async thread mappings
    const int a_m = tid >> 1;        // 0..63 (+64)
    const int a_c = tid & 1;         // A k-chunk (16B = 8 halves)
    const int b_c = tid & 15;        // B n-chunk
    const int b_k = tid >> 4;        // 0..7 (+8)

    auto issue_tile = [&](int kt) {
        const int s  = kt % STAGES;
        const int j  = kt >> 7;
        const int c0 = (kt & 127) * BK;
        const uint32_t As = sb + (uint32_t)(s * STAGE_B);
        const uint32_t Bs = As + ASZB;
        const __half* Ap = ApBase[j] + c0;
#pragma unroll
        for (int i = 0; i < 2; ++i) {
            const int m  = a_m + 64 * i;
            const int ch = a_c ^ ((m >> 2) & 1);
            cp16(As + (uint32_t)(m * 32 + ch * 16), Ap + (size_t)m * 2048 + a_c * 8);
        }
        const __half* Bp = Wh + (size_t)c0 * 16384 + (size_t)j * 2048 + bn * 128 + b_c * 8;
#pragma unroll
        for (int i = 0; i < 2; ++i) {
            const int k  = b_k + 8 * i;
            const int ch = b_c ^ (k & 7);
            cp16(Bs + (uint32_t)(k * 256 + ch * 16), Bp + (size_t)k * 16384);
        }
    };

    auto compute_tile = [&](int kt) {
        const int s = kt % STAGES;
        const uint32_t As = sb + (uint32_t)(s * STAGE_B);
        const uint32_t Bs = As + ASZB;
        uint32_t afr[4][4], bfr[4][4];
#pragma unroll
        for (int f = 0; f < 4; ++f) ldsm4(afr[f], As + aAddrOff[f]);
#pragma unroll
        for (int t = 0; t < 4; ++t) ldsm4t(bfr[t], Bs + bAddrOff[t]);
        // bfr[t]: r0,r1 = (b0,b1) for nf=2t ; r2,r3 = (b0,b1) for nf=2t+1
#pragma unroll
        for (int f = 0; f < 4; ++f)
#pragma unroll
            for (int t = 0; t < 4; ++t) {
                mma_f16(acc[f][2 * t    ], afr[f], bfr[t][0], bfr[t][1]);
                mma_f16(acc[f][2 * t + 1], afr[f], bfr[t][2], bfr[t][3]);
            }
    };

    // prologue: pairs 0 and 1 (tiles 0..3), one commit group per pair
    issue_tile(0); issue_tile(1); CP_COMMIT();
    issue_tile(2); issue_tile(3); CP_COMMIT();

    for (int p = 0; p < NPAIRS; ++p) {
        if (p < NPAIRS - 1) { CP_WAIT(1); } else { CP_WAIT(0); }
        __syncthreads();     // single barrier per pair; protects stage reuse

        if (p + 2 < NPAIRS) {
            issue_tile(2 * p + 4);
            issue_tile(2 * p + 5);
            CP_COMMIT();
        }

        compute_tile(2 * p);
        compute_tile(2 * p + 1);
        // no trailing barrier: next iteration's writes target pair p-1's
        // stages, which every warp finished before this iteration's barrier.
    }

    // ---- epilogue: add blade bias, store ----
    const int ccol = bn * 128 + wn * 64;
    const float* bp = bias + (size_t)kblk * 2048 + ccol;

#pragma unroll
    for (int nf = 0; nf < 8; ++nf) {
        const int cn = nf * 8 + 2 * q;
        const float b0 = bp[cn], b1 = bp[cn + 1];
#pragma unroll
        for (int f = 0; f < 4; ++f) {
            const int r0 = bm * 128 + wm * 64 + f * 16 + g;
            float2 lo  = make_float2(acc[f][nf][0] + b0, acc[f][nf][1] + b1);
            float2 hi2 = make_float2(acc[f][nf][2] + b0, acc[f][nf][3] + b1);
            *reinterpret_cast<float2*>(out + (size_t)r0 * 2048 + ccol + cn)       = lo;
            *reinterpret_cast<float2*>(out + (size_t)(r0 + 8) * 2048 + ccol + cn) = hi2;
        }
    }
}

extern "C" void kernel_launch(void* const* d_in, const int* in_sizes, int n_in,
                              void* d_out, int out_size)
{
    const float* X    = (const float*)d_in[0];
    const float* W    = (const float*)d_in[1];
    const float* bias = (const float*)d_in[2];
    float* out        = (float*)d_out;

    preconv_h<<<16384, 256>>>(X, W);

    cudaFuncSetAttribute(ga_f16_mma, cudaFuncAttributeMaxDynamicSharedMemorySize, SMEM_BYTES);
    dim3 grid(16, 128);
    ga_f16_mma<<<grid, NTHREADS, SMEM_BYTES>>>(bias, out);
}